// round 1
// baseline (speedup 1.0000x reference)
#include <cuda_runtime.h>

// Problem constants
#define Bq 4
#define Hh 8
#define Ll 512
#define Dd 512
#define HDd 64

// Scratch (device globals: no allocations allowed)
__device__ float g_Q[Bq * Ll * Dd];             // [B*L, H*HD] row-major
__device__ float g_K[Bq * Ll * Dd];
__device__ float g_V[Bq * Ll * Dd];
__device__ float g_O[Bq * Ll * Dd];
__device__ float g_S[Bq * Hh * Ll * Ll];        // per (b,h) contiguous 512x512
__device__ float g_A[Bq * Hh * Ll * Ll];
__device__ float g_T[Bq * Hh * Ll * Ll];
__device__ float g_dinv[Bq * Hh * Ll];

// ---------------------------------------------------------------------------
// Generic tiled fp32 GEMM: C = scale * A(MxK) @ B(KxN), row-major with ld's.
// Batched over gridDim.z; per-z offset = (z/Hn)*s?b + (z%Hn)*s?h.
// BM=BN=64, BK=16, 256 threads, 4x4 per thread. M%64==0, N%64==0, K%16==0.
// ---------------------------------------------------------------------------
__global__ __launch_bounds__(256) void gemm_nn(
    const float* __restrict__ A, const float* __restrict__ B, float* __restrict__ C,
    int M, int N, int K, int lda, int ldb, int ldc,
    long sAb, long sAh, long sBb, long sBh, long sCb, long sCh, int Hn,
    float scale)
{
    int z = blockIdx.z;
    int zb = z / Hn, zh = z % Hn;
    A += zb * sAb + zh * sAh;
    B += zb * sBb + zh * sBh;
    C += zb * sCb + zh * sCh;

    __shared__ float As[16][68];   // [k][m], padded
    __shared__ float Bs[16][64];   // [k][n]

    int tid = threadIdx.x;
    int tx = tid & 15, ty = tid >> 4;
    int row0 = blockIdx.y * 64, col0 = blockIdx.x * 64;

    float acc[4][4] = {};

    for (int k0 = 0; k0 < K; k0 += 16) {
#pragma unroll
        for (int t = 0; t < 4; t++) {
            int idx = tid + t * 256;           // 0..1023
            int r = idx >> 4, k = idx & 15;    // 64 x 16
            As[k][r] = A[(long)(row0 + r) * lda + k0 + k];
        }
#pragma unroll
        for (int t = 0; t < 4; t++) {
            int idx = tid + t * 256;
            int k = idx >> 6, c = idx & 63;    // 16 x 64
            Bs[k][c] = B[(long)(k0 + k) * ldb + col0 + c];
        }
        __syncthreads();
#pragma unroll
        for (int k = 0; k < 16; k++) {
            float4 av = *(const float4*)&As[k][ty * 4];
            float4 bv = *(const float4*)&Bs[k][tx * 4];
            float a[4] = {av.x, av.y, av.z, av.w};
            float b[4] = {bv.x, bv.y, bv.z, bv.w};
#pragma unroll
            for (int i = 0; i < 4; i++)
#pragma unroll
                for (int j = 0; j < 4; j++)
                    acc[i][j] += a[i] * b[j];
        }
        __syncthreads();
    }
#pragma unroll
    for (int i = 0; i < 4; i++)
#pragma unroll
        for (int j = 0; j < 4; j++)
            C[(long)(row0 + ty * 4 + i) * ldc + col0 + tx * 4 + j] = acc[i][j] * scale;
}

// ---------------------------------------------------------------------------
// C = A(MxK) @ B^T where B is (NxK) row-major  (for S = Q @ K^T)
// ---------------------------------------------------------------------------
__global__ __launch_bounds__(256) void gemm_nt(
    const float* __restrict__ A, const float* __restrict__ B, float* __restrict__ C,
    int M, int N, int K, int lda, int ldb, int ldc,
    long sAb, long sAh, long sBb, long sBh, long sCb, long sCh, int Hn,
    float scale)
{
    int z = blockIdx.z;
    int zb = z / Hn, zh = z % Hn;
    A += zb * sAb + zh * sAh;
    B += zb * sBb + zh * sBh;
    C += zb * sCb + zh * sCh;

    __shared__ float As[16][68];
    __shared__ float Bs[16][68];

    int tid = threadIdx.x;
    int tx = tid & 15, ty = tid >> 4;
    int row0 = blockIdx.y * 64, col0 = blockIdx.x * 64;

    float acc[4][4] = {};

    for (int k0 = 0; k0 < K; k0 += 16) {
#pragma unroll
        for (int t = 0; t < 4; t++) {
            int idx = tid + t * 256;
            int r = idx >> 4, k = idx & 15;
            As[k][r] = A[(long)(row0 + r) * lda + k0 + k];
        }
#pragma unroll
        for (int t = 0; t < 4; t++) {
            int idx = tid + t * 256;
            int c = idx >> 4, k = idx & 15;    // B row-major [N,K]
            Bs[k][c] = B[(long)(col0 + c) * ldb + k0 + k];
        }
        __syncthreads();
#pragma unroll
        for (int k = 0; k < 16; k++) {
            float4 av = *(const float4*)&As[k][ty * 4];
            float4 bv = *(const float4*)&Bs[k][tx * 4];
            float a[4] = {av.x, av.y, av.z, av.w};
            float b[4] = {bv.x, bv.y, bv.z, bv.w};
#pragma unroll
            for (int i = 0; i < 4; i++)
#pragma unroll
                for (int j = 0; j < 4; j++)
                    acc[i][j] += a[i] * b[j];
        }
        __syncthreads();
    }
#pragma unroll
    for (int i = 0; i < 4; i++)
#pragma unroll
        for (int j = 0; j < 4; j++)
            C[(long)(row0 + ty * 4 + i) * ldc + col0 + tx * 4 + j] = acc[i][j] * scale;
}

// ---------------------------------------------------------------------------
// Adjacency: A[i,k] = 1/(L*HD) * sum_j S[i,j]*S[k,j] * [S[i,j]*S[k,j] > RHO*HD]
// Symmetric: compute upper-triangular 64x64 tile pairs only, mirror write.
// Diagonal elements forced to zero.
// ---------------------------------------------------------------------------
__global__ __launch_bounds__(256) void adj_kernel(const float* __restrict__ S,
                                                  float* __restrict__ A)
{
    int z = blockIdx.z;
    const float* Sh = S + (long)z * Ll * Ll;
    float* Ah = A + (long)z * Ll * Ll;

    // map linear tile-pair index -> (ti, tk), ti <= tk, 8x8 tiles
    int rem = blockIdx.x;
    int ti = 0;
    while (rem >= (8 - ti)) { rem -= (8 - ti); ti++; }
    int tk = ti + rem;
    int i0 = ti * 64, k0 = tk * 64;

    __shared__ float Si[32][68];   // [j][i], padded so float4 rows stay 16B aligned
    __shared__ float Sk[32][68];

    int tid = threadIdx.x;
    int tx = tid & 15, ty = tid >> 4;
    const float THR = 0.1f * 64.0f;   // same predicate as U > RHO (exact pow2 scale)

    float acc[4][4] = {};

    for (int j0 = 0; j0 < Ll; j0 += 32) {
#pragma unroll
        for (int t = 0; t < 8; t++) {
            int li = tid + t * 256;         // 0..2047 = 64 rows x 32 j
            int i = li >> 5, j = li & 31;
            Si[j][i] = Sh[(long)(i0 + i) * Ll + j0 + j];
            Sk[j][i] = Sh[(long)(k0 + i) * Ll + j0 + j];
        }
        __syncthreads();
#pragma unroll
        for (int j = 0; j < 32; j++) {
            float4 av = *(const float4*)&Si[j][ty * 4];
            float4 bv = *(const float4*)&Sk[j][tx * 4];
            float a[4] = {av.x, av.y, av.z, av.w};
            float b[4] = {bv.x, bv.y, bv.z, bv.w};
#pragma unroll
            for (int ii = 0; ii < 4; ii++)
#pragma unroll
                for (int kk = 0; kk < 4; kk++) {
                    float t = a[ii] * b[kk];
                    if (t > THR) acc[ii][kk] += t;
                }
        }
        __syncthreads();
    }

    const float inv = 1.0f / (64.0f * 512.0f);
#pragma unroll
    for (int ii = 0; ii < 4; ii++)
#pragma unroll
        for (int kk = 0; kk < 4; kk++) {
            int gi = i0 + ty * 4 + ii, gk = k0 + tx * 4 + kk;
            float v = (gi == gk) ? 0.0f : acc[ii][kk] * inv;
            Ah[(long)gi * Ll + gk] = v;
            if (ti != tk) Ah[(long)gk * Ll + gi] = v;
        }
}

// ---------------------------------------------------------------------------
// Row sums of (A + I) -> dinv = rsqrt(clip(sum,1e-6))
// ---------------------------------------------------------------------------
__global__ __launch_bounds__(256) void rowsum_kernel(const float* __restrict__ A,
                                                     float* __restrict__ dinv)
{
    long row = blockIdx.x;
    const float* a = A + row * Ll;
    int t = threadIdx.x;
    float s = a[t] + a[t + 256];
#pragma unroll
    for (int o = 16; o > 0; o >>= 1) s += __shfl_xor_sync(0xFFFFFFFFu, s, o);
    __shared__ float red[8];
    if ((t & 31) == 0) red[t >> 5] = s;
    __syncthreads();
    if (t == 0) {
        float tot = 1.0f;   // +1 from identity (diag of A is 0)
        for (int w = 0; w < 8; w++) tot += red[w];
        tot = fmaxf(tot, 1e-6f);
        dinv[row] = rsqrtf(tot);
    }
}

// ---------------------------------------------------------------------------
// A_hat[i,k] = dinv[i] * (A[i,k] + (i==k)) * dinv[k]  (in-place)
// ---------------------------------------------------------------------------
__global__ __launch_bounds__(256) void ahat_kernel(float* __restrict__ A,
                                                   const float* __restrict__ dinv)
{
    long n = (long)Bq * Hh * Ll * Ll;
    for (long x = (long)blockIdx.x * blockDim.x + threadIdx.x; x < n;
         x += (long)gridDim.x * blockDim.x) {
        long z = x / ((long)Ll * Ll);
        int r = (int)((x / Ll) % Ll);
        int c = (int)(x % Ll);
        float v = A[x] + (r == c ? 1.0f : 0.0f);
        A[x] = v * dinv[z * Ll + r] * dinv[z * Ll + c];
    }
}

// ---------------------------------------------------------------------------
// Row-wise softmax over the last dim (512), in place. One block per row.
// ---------------------------------------------------------------------------
__global__ __launch_bounds__(256) void softmax_kernel(float* __restrict__ S)
{
    long row = blockIdx.x;
    float* s = S + row * Ll;
    int t = threadIdx.x;
    float v0 = s[t], v1 = s[t + 256];

    __shared__ float red[8];
    float m = fmaxf(v0, v1);
#pragma unroll
    for (int o = 16; o > 0; o >>= 1) m = fmaxf(m, __shfl_xor_sync(0xFFFFFFFFu, m, o));
    if ((t & 31) == 0) red[t >> 5] = m;
    __syncthreads();
    float mm = red[0];
#pragma unroll
    for (int w = 1; w < 8; w++) mm = fmaxf(mm, red[w]);
    __syncthreads();

    float e0 = expf(v0 - mm), e1 = expf(v1 - mm);
    float ssum = e0 + e1;
#pragma unroll
    for (int o = 16; o > 0; o >>= 1) ssum += __shfl_xor_sync(0xFFFFFFFFu, ssum, o);
    if ((t & 31) == 0) red[t >> 5] = ssum;
    __syncthreads();
    float tot = 0.0f;
#pragma unroll
    for (int w = 0; w < 8; w++) tot += red[w];
    float inv = 1.0f / tot;
    s[t] = e0 * inv;
    s[t + 256] = e1 * inv;
}

// ---------------------------------------------------------------------------
extern "C" void kernel_launch(void* const* d_in, const int* in_sizes, int n_in,
                              void* d_out, int out_size)
{
    const float* x  = (const float*)d_in[0];
    const float* Wq = (const float*)d_in[1];
    const float* Wk = (const float*)d_in[2];
    const float* Wv = (const float*)d_in[3];
    const float* Wo = (const float*)d_in[4];
    float* out = (float*)d_out;

    float *Qp, *Kp, *Vp, *Op, *Sp, *Ap, *Tp, *Dp;
    cudaGetSymbolAddress((void**)&Qp, g_Q);
    cudaGetSymbolAddress((void**)&Kp, g_K);
    cudaGetSymbolAddress((void**)&Vp, g_V);
    cudaGetSymbolAddress((void**)&Op, g_O);
    cudaGetSymbolAddress((void**)&Sp, g_S);
    cudaGetSymbolAddress((void**)&Ap, g_A);
    cudaGetSymbolAddress((void**)&Tp, g_T);
    cudaGetSymbolAddress((void**)&Dp, g_dinv);

    const long LD   = (long)Ll * Dd;        // 262144: per-batch stride of [B*L,512] mats
    const long LL   = (long)Ll * Ll;        // 262144: per-head S/A/T tile
    const long HLL  = (long)Hh * LL;        // per-batch stride of S/A/T

    // 1) Q,K,V projections: [2048,512] = x @ W
    {
        dim3 g(Dd / 64, (Bq * Ll) / 64, 1);
        gemm_nn<<<g, 256>>>(x, Wq, Qp, Bq * Ll, Dd, Dd, Dd, Dd, Dd,
                            0, 0, 0, 0, 0, 0, 1, 1.0f);
        gemm_nn<<<g, 256>>>(x, Wk, Kp, Bq * Ll, Dd, Dd, Dd, Dd, Dd,
                            0, 0, 0, 0, 0, 0, 1, 1.0f);
        gemm_nn<<<g, 256>>>(x, Wv, Vp, Bq * Ll, Dd, Dd, Dd, Dd, Dd,
                            0, 0, 0, 0, 0, 0, 1, 1.0f);
    }

    // 2) S = Q @ K^T per head (head views: lda=512, batch stride L*512, head stride 64)
    {
        dim3 g(Ll / 64, Ll / 64, Bq * Hh);
        gemm_nt<<<g, 256>>>(Qp, Kp, Sp, Ll, Ll, HDd, Dd, Dd, Ll,
                            LD, 64, LD, 64, HLL, LL, Hh, 1.0f);
    }

    // 3) adjacency (symmetric, upper-tri tile pairs)
    adj_kernel<<<dim3(36, 1, Bq * Hh), 256>>>(Sp, Ap);

    // 4) degree rsqrt
    rowsum_kernel<<<Bq * Hh * Ll, 256>>>(Ap, Dp);

    // 5) A_hat (in place over A)
    ahat_kernel<<<4096, 256>>>(Ap, Dp);

    // 6) T = A_hat @ S
    {
        dim3 g(Ll / 64, Ll / 64, Bq * Hh);
        gemm_nn<<<g, 256>>>(Ap, Sp, Tp, Ll, Ll, Ll, Ll, Ll, Ll,
                            HLL, LL, HLL, LL, HLL, LL, Hh, 1.0f);
        // 7) S_jump = (T @ A_hat) / sqrt(HD)   (A_hat symmetric) -> overwrite S
        gemm_nn<<<g, 256>>>(Tp, Ap, Sp, Ll, Ll, Ll, Ll, Ll, Ll,
                            HLL, LL, HLL, LL, HLL, LL, Hh, 0.125f);
    }

    // 8) softmax rows of S_jump (in place)
    softmax_kernel<<<Bq * Hh * Ll, 256>>>(Sp);

    // 9) O = attn @ V per head -> [B*L, H*HD] layout
    {
        dim3 g(1, Ll / 64, Bq * Hh);
        gemm_nn<<<g, 256>>>(Sp, Vp, Op, Ll, HDd, Ll, Ll, Dd, Dd,
                            HLL, LL, LD, 64, LD, 64, Hh, 1.0f);
    }

    // 10) out = O @ Wo
    {
        dim3 g(Dd / 64, (Bq * Ll) / 64, 1);
        gemm_nn<<<g, 256>>>(Op, Wo, out, Bq * Ll, Dd, Dd, Dd, Dd, Dd,
                            0, 0, 0, 0, 0, 0, 1, 1.0f);
    }
}

// round 7
// speedup vs baseline: 1.3765x; 1.3765x over previous
#include <cuda_runtime.h>
#include <cuda_bf16.h>
#include <cstdint>

// Problem constants
#define Bq 4
#define Hh 8
#define Ll 512
#define Dd 512
#define HDd 64
#define ZZ (Bq * Hh)
#define LL2 ((long)Ll * Ll)

// fp32 scratch
__device__ float g_Q[Bq * Ll * Dd];
__device__ float g_K[Bq * Ll * Dd];
__device__ float g_V[Bq * Ll * Dd];
__device__ float g_O[Bq * Ll * Dd];
__device__ float g_S[ZZ * Ll * Ll];
__device__ float g_A[ZZ * Ll * Ll];
__device__ float g_dinv[ZZ * Ll];

// bf16 split scratch
__device__ __align__(16) __nv_bfloat16 g_Ah_hi[ZZ * Ll * Ll];
__device__ __align__(16) __nv_bfloat16 g_Ah_lo[ZZ * Ll * Ll];
__device__ __align__(16) __nv_bfloat16 g_ST_hi[ZZ * Ll * Ll];
__device__ __align__(16) __nv_bfloat16 g_ST_lo[ZZ * Ll * Ll];
__device__ __align__(16) __nv_bfloat16 g_T_hi[ZZ * Ll * Ll];
__device__ __align__(16) __nv_bfloat16 g_T_lo[ZZ * Ll * Ll];

// ===========================================================================
// mma.sync helpers (baseline PTX — compiles at compute_103, no 'a' features)
// ===========================================================================
__device__ __forceinline__ uint32_t smem_u32(const void* p) {
    uint32_t a;
    asm("{ .reg .u64 t; cvta.to.shared.u64 t, %1; cvt.u32.u64 %0, t; }"
        : "=r"(a) : "l"(p));
    return a;
}

__device__ __forceinline__ void ldsm_x4(uint32_t addr, uint32_t* r) {
    asm volatile("ldmatrix.sync.aligned.m8n8.x4.shared.b16 {%0,%1,%2,%3}, [%4];"
                 : "=r"(r[0]), "=r"(r[1]), "=r"(r[2]), "=r"(r[3]) : "r"(addr));
}

__device__ __forceinline__ void mma_bf16(float* c, const uint32_t* a,
                                         const uint32_t* b) {
    asm volatile(
        "mma.sync.aligned.m16n8k16.row.col.f32.bf16.bf16.f32 "
        "{%0,%1,%2,%3}, {%4,%5,%6,%7}, {%8,%9}, {%0,%1,%2,%3};"
        : "+f"(c[0]), "+f"(c[1]), "+f"(c[2]), "+f"(c[3])
        : "r"(a[0]), "r"(a[1]), "r"(a[2]), "r"(a[3]), "r"(b[0]), "r"(b[1]));
}

// ===========================================================================
// Split-bf16 tensor-core GEMM via mma.sync: per z, C[i,n] = sum_k A[i,k]*B[n,k]
// A = Ahi+Alo, B = Bhi+Blo, row-major [512,512] per z (both K-major).
// CTA tile 128x128, 8 warps (32x64 each), K-chunks of 32.
// mode 0: write hi/lo bf16 split of C.  mode 1: write fp32 C*scale.
// ===========================================================================
#define PADR 40   // smem row stride in bf16 (80 B: 20-bank skew, conflict-free)

__global__ __launch_bounds__(256, 2) void tc_gemm(
    const __nv_bfloat16* __restrict__ Ahi, const __nv_bfloat16* __restrict__ Alo,
    const __nv_bfloat16* __restrict__ Bhi, const __nv_bfloat16* __restrict__ Blo,
    __nv_bfloat16* __restrict__ Ohi, __nv_bfloat16* __restrict__ Olo,
    float* __restrict__ Of32, float scale, int mode)
{
    __shared__ __align__(16) __nv_bfloat16 sAH[128 * PADR];
    __shared__ __align__(16) __nv_bfloat16 sAL[128 * PADR];
    __shared__ __align__(16) __nv_bfloat16 sBH[128 * PADR];
    __shared__ __align__(16) __nv_bfloat16 sBL[128 * PADR];

    int z = blockIdx.z;
    long zo = (long)z * LL2;
    int row0 = blockIdx.y * 128, col0 = blockIdx.x * 128;
    int tid = threadIdx.x, lane = tid & 31, wid = tid >> 5;
    int wm = wid & 3, wn = wid >> 2;       // warp tile: rows wm*32, cols wn*64

    uint32_t aHb = smem_u32(sAH), aLb = smem_u32(sAL);
    uint32_t bHb = smem_u32(sBH), bLb = smem_u32(sBL);

    float acc[2][8][4];
#pragma unroll
    for (int i = 0; i < 2; i++)
#pragma unroll
        for (int j = 0; j < 8; j++)
#pragma unroll
            for (int k = 0; k < 4; k++) acc[i][j][k] = 0.0f;

    // ldmatrix lane addressing (constant across k-chunks)
    int a_r = (lane & 15);                    // A tile row within atom
    int a_c = ((lane >> 4) << 3);             // +8 cols for lanes 16-31
    int b_r = ((lane >> 4) << 3) + (lane & 7);
    int b_c = (((lane >> 3) & 1) << 3);

    for (int kc = 0; kc < 16; kc++) {
        int k0 = kc * 32;
        __syncthreads();   // previous iter's readers done before overwrite
#pragma unroll
        for (int t = 0; t < 2; t++) {
            int idx = tid + t * 256;
            int r = idx >> 2, v = idx & 3;
            long ga = zo + (long)(row0 + r) * Ll + k0 + v * 8;
            long gb = zo + (long)(col0 + r) * Ll + k0 + v * 8;
            *(uint4*)(sAH + r * PADR + v * 8) = *(const uint4*)(Ahi + ga);
            *(uint4*)(sAL + r * PADR + v * 8) = *(const uint4*)(Alo + ga);
            *(uint4*)(sBH + r * PADR + v * 8) = *(const uint4*)(Bhi + gb);
            *(uint4*)(sBL + r * PADR + v * 8) = *(const uint4*)(Blo + gb);
        }
        __syncthreads();

#pragma unroll
        for (int ks = 0; ks < 2; ks++) {
            int kb = ks * 16;
            uint32_t aH[2][4], aL[2][4];
#pragma unroll
            for (int am = 0; am < 2; am++) {
                uint32_t off =
                    (uint32_t)((wm * 32 + am * 16 + a_r) * PADR + kb + a_c) * 2;
                ldsm_x4(aHb + off, aH[am]);
                ldsm_x4(aLb + off, aL[am]);
            }
#pragma unroll
            for (int bp = 0; bp < 4; bp++) {
                uint32_t boff =
                    (uint32_t)((wn * 64 + bp * 16 + b_r) * PADR + kb + b_c) * 2;
                uint32_t bH[4], bL[4];
                ldsm_x4(bHb + boff, bH);
                ldsm_x4(bLb + boff, bL);
#pragma unroll
                for (int am = 0; am < 2; am++)
#pragma unroll
                    for (int bna = 0; bna < 2; bna++) {
                        float* c = acc[am][bp * 2 + bna];
                        mma_bf16(c, aH[am], bH + bna * 2);
                        mma_bf16(c, aH[am], bL + bna * 2);
                        mma_bf16(c, aL[am], bH + bna * 2);
                    }
            }
        }
    }

    // Epilogue. C fragment: c0=(r, c), c1=(r, c+1), c2=(r+8, c), c3=(r+8, c+1)
    int r_base = row0 + wm * 32 + (lane >> 2);
    int c_base = col0 + wn * 64 + 2 * (lane & 3);
#pragma unroll
    for (int am = 0; am < 2; am++)
#pragma unroll
        for (int bn = 0; bn < 8; bn++) {
            int r = r_base + am * 16;
            int c = c_base + bn * 8;
            const float* a = acc[am][bn];
            if (mode == 0) {
#pragma unroll
                for (int hrow = 0; hrow < 2; hrow++) {
                    float f0 = a[hrow * 2], f1 = a[hrow * 2 + 1];
                    __nv_bfloat16 h0 = __float2bfloat16(f0);
                    __nv_bfloat16 h1 = __float2bfloat16(f1);
                    __nv_bfloat16 l0 = __float2bfloat16(f0 - __bfloat162float(h0));
                    __nv_bfloat16 l1 = __float2bfloat16(f1 - __bfloat162float(h1));
                    long o = zo + (long)(r + hrow * 8) * Ll + c;
                    *(__nv_bfloat162*)(Ohi + o) = __halves2bfloat162(h0, h1);
                    *(__nv_bfloat162*)(Olo + o) = __halves2bfloat162(l0, l1);
                }
            } else {
#pragma unroll
                for (int hrow = 0; hrow < 2; hrow++) {
                    long o = zo + (long)(r + hrow * 8) * Ll + c;
                    float2 f2;
                    f2.x = a[hrow * 2] * scale;
                    f2.y = a[hrow * 2 + 1] * scale;
                    *(float2*)(Of32 + o) = f2;
                }
            }
        }
}

// ===========================================================================
// Fused A_hat + split: reads raw adjacency A and dinv, writes bf16 hi/lo of
// A_hat = dinv_r * (A + I) * dinv_c directly (fp32 A_hat never materialized).
// ===========================================================================
__global__ __launch_bounds__(256) void ahat_split_kernel(
    const float* __restrict__ A, const float* __restrict__ dinv,
    __nv_bfloat16* __restrict__ hi, __nv_bfloat16* __restrict__ lo)
{
    long n4 = (long)ZZ * Ll * Ll / 4;
    for (long i = (long)blockIdx.x * blockDim.x + threadIdx.x; i < n4;
         i += (long)gridDim.x * blockDim.x) {
        long x = i * 4;
        long z = x >> 18;
        int r = (int)((x >> 9) & 511);
        int c = (int)(x & 511);
        float dr = dinv[z * Ll + r];
        const float* dc = dinv + z * Ll + c;
        float4 v = ((const float4*)A)[i];
        float f[4] = { v.x, v.y, v.z, v.w };
#pragma unroll
        for (int j = 0; j < 4; j++) {
            float a = f[j] + ((c + j) == r ? 1.0f : 0.0f);
            f[j] = a * dr * dc[j];
        }
        __nv_bfloat16 h[4], l[4];
#pragma unroll
        for (int j = 0; j < 4; j++) {
            h[j] = __float2bfloat16(f[j]);
            l[j] = __float2bfloat16(f[j] - __bfloat162float(h[j]));
        }
        ((__nv_bfloat162*)hi)[2 * i]     = __halves2bfloat162(h[0], h[1]);
        ((__nv_bfloat162*)hi)[2 * i + 1] = __halves2bfloat162(h[2], h[3]);
        ((__nv_bfloat162*)lo)[2 * i]     = __halves2bfloat162(l[0], l[1]);
        ((__nv_bfloat162*)lo)[2 * i + 1] = __halves2bfloat162(l[2], l[3]);
    }
}

// transpose + split: out[z][c][r] = split(S[z][r][c])
__global__ __launch_bounds__(256) void split_trans_kernel(
    const float* __restrict__ S, __nv_bfloat16* __restrict__ hi,
    __nv_bfloat16* __restrict__ lo)
{
    __shared__ float t[32][33];
    int z = blockIdx.z;
    long zo = (long)z * LL2;
    int c0 = blockIdx.x * 32, r0 = blockIdx.y * 32;
    int tx = threadIdx.x & 31, ty = threadIdx.x >> 5;
#pragma unroll
    for (int i = 0; i < 4; i++)
        t[ty + i * 8][tx] = S[zo + (long)(r0 + ty + i * 8) * Ll + c0 + tx];
    __syncthreads();
#pragma unroll
    for (int i = 0; i < 4; i++) {
        float v = t[tx][ty + i * 8];
        __nv_bfloat16 h = __float2bfloat16(v);
        __nv_bfloat16 l = __float2bfloat16(v - __bfloat162float(h));
        long o = zo + (long)(c0 + ty + i * 8) * Ll + r0 + tx;
        hi[o] = h;
        lo[o] = l;
    }
}

// ===========================================================================
// fp32 SIMT kernels
// ===========================================================================
__global__ __launch_bounds__(256) void gemm_nn(
    const float* __restrict__ A, const float* __restrict__ B, float* __restrict__ C,
    int M, int N, int K, int lda, int ldb, int ldc,
    long sAb, long sAh, long sBb, long sBh, long sCb, long sCh, int Hn,
    float scale)
{
    int z = blockIdx.z;
    int zb = z / Hn, zh = z % Hn;
    A += zb * sAb + zh * sAh;
    B += zb * sBb + zh * sBh;
    C += zb * sCb + zh * sCh;

    __shared__ float As[16][68];
    __shared__ float Bs[16][64];

    int tid = threadIdx.x;
    int tx = tid & 15, ty = tid >> 4;
    int row0 = blockIdx.y * 64, col0 = blockIdx.x * 64;

    float acc[4][4] = {};

    for (int k0 = 0; k0 < K; k0 += 16) {
#pragma unroll
        for (int t = 0; t < 4; t++) {
            int idx = tid + t * 256;
            int r = idx >> 4, k = idx & 15;
            As[k][r] = A[(long)(row0 + r) * lda + k0 + k];
        }
#pragma unroll
        for (int t = 0; t < 4; t++) {
            int idx = tid + t * 256;
            int k = idx >> 6, c = idx & 63;
            Bs[k][c] = B[(long)(k0 + k) * ldb + col0 + c];
        }
        __syncthreads();
#pragma unroll
        for (int k = 0; k < 16; k++) {
            float4 av = *(const float4*)&As[k][ty * 4];
            float4 bv = *(const float4*)&Bs[k][tx * 4];
            float a[4] = {av.x, av.y, av.z, av.w};
            float b[4] = {bv.x, bv.y, bv.z, bv.w};
#pragma unroll
            for (int i = 0; i < 4; i++)
#pragma unroll
                for (int j = 0; j < 4; j++)
                    acc[i][j] += a[i] * b[j];
        }
        __syncthreads();
    }
#pragma unroll
    for (int i = 0; i < 4; i++)
#pragma unroll
        for (int j = 0; j < 4; j++)
            C[(long)(row0 + ty * 4 + i) * ldc + col0 + tx * 4 + j] = acc[i][j] * scale;
}

__global__ __launch_bounds__(256) void gemm_nt(
    const float* __restrict__ A, const float* __restrict__ B, float* __restrict__ C,
    int M, int N, int K, int lda, int ldb, int ldc,
    long sAb, long sAh, long sBb, long sBh, long sCb, long sCh, int Hn,
    float scale)
{
    int z = blockIdx.z;
    int zb = z / Hn, zh = z % Hn;
    A += zb * sAb + zh * sAh;
    B += zb * sBb + zh * sBh;
    C += zb * sCb + zh * sCh;

    __shared__ float As[16][68];
    __shared__ float Bs[16][68];

    int tid = threadIdx.x;
    int tx = tid & 15, ty = tid >> 4;
    int row0 = blockIdx.y * 64, col0 = blockIdx.x * 64;

    float acc[4][4] = {};

    for (int k0 = 0; k0 < K; k0 += 16) {
#pragma unroll
        for (int t = 0; t < 4; t++) {
            int idx = tid + t * 256;
            int r = idx >> 4, k = idx & 15;
            As[k][r] = A[(long)(row0 + r) * lda + k0 + k];
        }
#pragma unroll
        for (int t = 0; t < 4; t++) {
            int idx = tid + t * 256;
            int c = idx >> 4, k = idx & 15;
            Bs[k][c] = B[(long)(col0 + c) * ldb + k0 + k];
        }
        __syncthreads();
#pragma unroll
        for (int k = 0; k < 16; k++) {
            float4 av = *(const float4*)&As[k][ty * 4];
            float4 bv = *(const float4*)&Bs[k][tx * 4];
            float a[4] = {av.x, av.y, av.z, av.w};
            float b[4] = {bv.x, bv.y, bv.z, bv.w};
#pragma unroll
            for (int i = 0; i < 4; i++)
#pragma unroll
                for (int j = 0; j < 4; j++)
                    acc[i][j] += a[i] * b[j];
        }
        __syncthreads();
    }
#pragma unroll
    for (int i = 0; i < 4; i++)
#pragma unroll
        for (int j = 0; j < 4; j++)
            C[(long)(row0 + ty * 4 + i) * ldc + col0 + tx * 4 + j] = acc[i][j] * scale;
}

__global__ __launch_bounds__(256) void adj_kernel(const float* __restrict__ S,
                                                  float* __restrict__ A)
{
    int z = blockIdx.z;
    const float* Sh = S + (long)z * Ll * Ll;
    float* Ah = A + (long)z * Ll * Ll;

    int rem = blockIdx.x;
    int ti = 0;
    while (rem >= (8 - ti)) { rem -= (8 - ti); ti++; }
    int tk = ti + rem;
    int i0 = ti * 64, k0 = tk * 64;

    __shared__ float Si[32][68];
    __shared__ float Sk[32][68];

    int tid = threadIdx.x;
    int tx = tid & 15, ty = tid >> 4;
    const float THR = 0.1f * 64.0f;

    float acc[4][4] = {};

    for (int j0 = 0; j0 < Ll; j0 += 32) {
#pragma unroll
        for (int t = 0; t < 8; t++) {
            int li = tid + t * 256;
            int i = li >> 5, j = li & 31;
            Si[j][i] = Sh[(long)(i0 + i) * Ll + j0 + j];
            Sk[j][i] = Sh[(long)(k0 + i) * Ll + j0 + j];
        }
        __syncthreads();
#pragma unroll
        for (int j = 0; j < 32; j++) {
            float4 av = *(const float4*)&Si[j][ty * 4];
            float4 bv = *(const float4*)&Sk[j][tx * 4];
            float a[4] = {av.x, av.y, av.z, av.w};
            float b[4] = {bv.x, bv.y, bv.z, bv.w};
#pragma unroll
            for (int ii = 0; ii < 4; ii++)
#pragma unroll
                for (int kk = 0; kk < 4; kk++) {
                    float t = a[ii] * b[kk];
                    if (t > THR) acc[ii][kk] += t;
                }
        }
        __syncthreads();
    }

    const float inv = 1.0f / (64.0f * 512.0f);
#pragma unroll
    for (int ii = 0; ii < 4; ii++)
#pragma unroll
        for (int kk = 0; kk < 4; kk++) {
            int gi = i0 + ty * 4 + ii, gk = k0 + tx * 4 + kk;
            float v = (gi == gk) ? 0.0f : acc[ii][kk] * inv;
            Ah[(long)gi * Ll + gk] = v;
            if (ti != tk) Ah[(long)gk * Ll + gi] = v;
        }
}

__global__ __launch_bounds__(256) void rowsum_kernel(const float* __restrict__ A,
                                                     float* __restrict__ dinv)
{
    long row = blockIdx.x;
    const float* a = A + row * Ll;
    int t = threadIdx.x;
    float s = a[t] + a[t + 256];
#pragma unroll
    for (int o = 16; o > 0; o >>= 1) s += __shfl_xor_sync(0xFFFFFFFFu, s, o);
    __shared__ float red[8];
    if ((t & 31) == 0) red[t >> 5] = s;
    __syncthreads();
    if (t == 0) {
        float tot = 1.0f;
        for (int w = 0; w < 8; w++) tot += red[w];
        tot = fmaxf(tot, 1e-6f);
        dinv[row] = rsqrtf(tot);
    }
}

__global__ __launch_bounds__(256) void softmax_kernel(float* __restrict__ S)
{
    long row = blockIdx.x;
    float* s = S + row * Ll;
    int t = threadIdx.x;
    float v0 = s[t], v1 = s[t + 256];

    __shared__ float red[8];
    float m = fmaxf(v0, v1);
#pragma unroll
    for (int o = 16; o > 0; o >>= 1) m = fmaxf(m, __shfl_xor_sync(0xFFFFFFFFu, m, o));
    if ((t & 31) == 0) red[t >> 5] = m;
    __syncthreads();
    float mm = red[0];
#pragma unroll
    for (int w = 1; w < 8; w++) mm = fmaxf(mm, red[w]);
    __syncthreads();

    float e0 = expf(v0 - mm), e1 = expf(v1 - mm);
    float ssum = e0 + e1;
#pragma unroll
    for (int o = 16; o > 0; o >>= 1) ssum += __shfl_xor_sync(0xFFFFFFFFu, ssum, o);
    if ((t & 31) == 0) red[t >> 5] = ssum;
    __syncthreads();
    float tot = 0.0f;
#pragma unroll
    for (int w = 0; w < 8; w++) tot += red[w];
    float inv = 1.0f / tot;
    s[t] = e0 * inv;
    s[t + 256] = e1 * inv;
}

// ===========================================================================
extern "C" void kernel_launch(void* const* d_in, const int* in_sizes, int n_in,
                              void* d_out, int out_size)
{
    const float* x  = (const float*)d_in[0];
    const float* Wq = (const float*)d_in[1];
    const float* Wk = (const float*)d_in[2];
    const float* Wv = (const float*)d_in[3];
    const float* Wo = (const float*)d_in[4];
    float* out = (float*)d_out;

    float *Qp, *Kp, *Vp, *Op, *Sp, *Ap, *Dp;
    cudaGetSymbolAddress((void**)&Qp, g_Q);
    cudaGetSymbolAddress((void**)&Kp, g_K);
    cudaGetSymbolAddress((void**)&Vp, g_V);
    cudaGetSymbolAddress((void**)&Op, g_O);
    cudaGetSymbolAddress((void**)&Sp, g_S);
    cudaGetSymbolAddress((void**)&Ap, g_A);
    cudaGetSymbolAddress((void**)&Dp, g_dinv);

    __nv_bfloat16 *AhH, *AhL, *STH, *STL, *TH, *TL;
    cudaGetSymbolAddress((void**)&AhH, g_Ah_hi);
    cudaGetSymbolAddress((void**)&AhL, g_Ah_lo);
    cudaGetSymbolAddress((void**)&STH, g_ST_hi);
    cudaGetSymbolAddress((void**)&STL, g_ST_lo);
    cudaGetSymbolAddress((void**)&TH, g_T_hi);
    cudaGetSymbolAddress((void**)&TL, g_T_lo);

    const long LD  = (long)Ll * Dd;
    const long LL  = (long)Ll * Ll;
    const long HLL = (long)Hh * LL;

    // 1) Q,K,V projections
    {
        dim3 g(Dd / 64, (Bq * Ll) / 64, 1);
        gemm_nn<<<g, 256>>>(x, Wq, Qp, Bq * Ll, Dd, Dd, Dd, Dd, Dd,
                            0, 0, 0, 0, 0, 0, 1, 1.0f);
        gemm_nn<<<g, 256>>>(x, Wk, Kp, Bq * Ll, Dd, Dd, Dd, Dd, Dd,
                            0, 0, 0, 0, 0, 0, 1, 1.0f);
        gemm_nn<<<g, 256>>>(x, Wv, Vp, Bq * Ll, Dd, Dd, Dd, Dd, Dd,
                            0, 0, 0, 0, 0, 0, 1, 1.0f);
    }

    // 2) S = Q @ K^T per head (exact fp32 — feeds the threshold predicate)
    {
        dim3 g(Ll / 64, Ll / 64, ZZ);
        gemm_nt<<<g, 256>>>(Qp, Kp, Sp, Ll, Ll, HDd, Dd, Dd, Ll,
                            LD, 64, LD, 64, HLL, LL, Hh, 1.0f);
    }

    // 3) adjacency (raw, unnormalized; zero diag)
    adj_kernel<<<dim3(36, 1, ZZ), 256>>>(Sp, Ap);

    // 4) degree rsqrt
    rowsum_kernel<<<ZZ * Ll, 256>>>(Ap, Dp);

    // 5) fused A_hat + bf16 hi/lo split (fp32 A_hat never written)
    ahat_split_kernel<<<4096, 256>>>(Ap, Dp, AhH, AhL);

    // 6) S transpose + split for GEMM1's B operand
    split_trans_kernel<<<dim3(16, 16, ZZ), 256>>>(Sp, STH, STL);

    // 7) T = A_hat @ S (mma.sync split bf16) -> T hi/lo
    {
        dim3 g(4, 4, ZZ);
        tc_gemm<<<g, 256>>>(AhH, AhL, STH, STL, TH, TL, nullptr, 1.0f, 0);
        // 8) S_jump = (T @ A_hat) / sqrt(HD) -> overwrite g_S (fp32)
        tc_gemm<<<g, 256>>>(TH, TL, AhH, AhL, nullptr, nullptr, Sp, 0.125f, 1);
    }

    // 9) softmax
    softmax_kernel<<<ZZ * Ll, 256>>>(Sp);

    // 10) O = attn @ V
    {
        dim3 g(1, Ll / 64, ZZ);
        gemm_nn<<<g, 256>>>(Sp, Vp, Op, Ll, HDd, Ll, Ll, Dd, Dd,
                            HLL, LL, LD, 64, LD, 64, Hh, 1.0f);
    }

    // 11) out = O @ Wo
    {
        dim3 g(Dd / 64, (Bq * Ll) / 64, 1);
        gemm_nn<<<g, 256>>>(Op, Wo, out, Bq * Ll, Dd, Dd, Dd, Dd, Dd,
                            0, 0, 0, 0, 0, 0, 1, 1.0f);
    }
}

// round 12
// speedup vs baseline: 1.6955x; 1.2317x over previous
#include <cuda_runtime.h>
#include <cuda_bf16.h>
#include <cstdint>

// Problem constants
#define Bq 4
#define Hh 8
#define Ll 512
#define Dd 512
#define HDd 64
#define ZZ (Bq * Hh)
#define LL2 ((long)Ll * Ll)

// fp32 scratch
__device__ float g_S[ZZ * Ll * Ll];
__device__ float g_A[ZZ * Ll * Ll];
__device__ float g_dinv[ZZ * Ll];

// bf16 split scratch
__device__ __align__(16) __nv_bfloat16 g_x_hi[Bq * Ll * Dd];
__device__ __align__(16) __nv_bfloat16 g_x_lo[Bq * Ll * Dd];
__device__ __align__(16) __nv_bfloat16 g_WT_hi[4 * Dd * Dd];   // WqT|WkT|WvT|WoT
__device__ __align__(16) __nv_bfloat16 g_WT_lo[4 * Dd * Dd];
__device__ __align__(16) __nv_bfloat16 g_QKV_hi[Bq * Ll * 3 * Dd];
__device__ __align__(16) __nv_bfloat16 g_QKV_lo[Bq * Ll * 3 * Dd];
__device__ __align__(16) __nv_bfloat16 g_VT_hi[ZZ * HDd * Ll];
__device__ __align__(16) __nv_bfloat16 g_VT_lo[ZZ * HDd * Ll];
__device__ __align__(16) __nv_bfloat16 g_Ah_hi[ZZ * Ll * Ll];
__device__ __align__(16) __nv_bfloat16 g_Ah_lo[ZZ * Ll * Ll];
__device__ __align__(16) __nv_bfloat16 g_ST_hi[ZZ * Ll * Ll];  // S^T, later attn
__device__ __align__(16) __nv_bfloat16 g_ST_lo[ZZ * Ll * Ll];
__device__ __align__(16) __nv_bfloat16 g_T_hi[ZZ * Ll * Ll];   // T, later O
__device__ __align__(16) __nv_bfloat16 g_T_lo[ZZ * Ll * Ll];

// ===========================================================================
// mma.sync helpers (baseline PTX — compiles at compute_103)
// ===========================================================================
__device__ __forceinline__ uint32_t smem_u32(const void* p) {
    uint32_t a;
    asm("{ .reg .u64 t; cvta.to.shared.u64 t, %1; cvt.u32.u64 %0, t; }"
        : "=r"(a) : "l"(p));
    return a;
}

__device__ __forceinline__ void ldsm_x4(uint32_t addr, uint32_t* r) {
    asm volatile("ldmatrix.sync.aligned.m8n8.x4.shared.b16 {%0,%1,%2,%3}, [%4];"
                 : "=r"(r[0]), "=r"(r[1]), "=r"(r[2]), "=r"(r[3]) : "r"(addr));
}

__device__ __forceinline__ void mma_bf16(float* c, const uint32_t* a,
                                         const uint32_t* b) {
    asm volatile(
        "mma.sync.aligned.m16n8k16.row.col.f32.bf16.bf16.f32 "
        "{%0,%1,%2,%3}, {%4,%5,%6,%7}, {%8,%9}, {%0,%1,%2,%3};"
        : "+f"(c[0]), "+f"(c[1]), "+f"(c[2]), "+f"(c[3])
        : "r"(a[0]), "r"(a[1]), "r"(a[2]), "r"(a[3]), "r"(b[0]), "r"(b[1]));
}

#define CP_ASYNC16(saddr, gptr) \
    asm volatile("cp.async.cg.shared.global [%0], [%1], 16;" \
        :: "r"(saddr), "l"(gptr) : "memory")
#define CP_COMMIT() asm volatile("cp.async.commit_group;" ::: "memory")
#define CP_WAIT1()  asm volatile("cp.async.wait_group 1;" ::: "memory")
#define CP_WAIT0()  asm volatile("cp.async.wait_group 0;" ::: "memory")

// ===========================================================================
// Generalized split-bf16 TC GEMM (NT form): per z, C[i,n] = sum_k A[i,k]*B[n,k]
// A = Ahi+Alo, B = Bhi+Blo. Template AM: 2 -> N-tile 128, 1 -> N-tile 64.
// CTA M-tile 128. K multiple of 32. cp.async double-buffered.
// mode 0: write bf16 hi/lo split of C.  mode 1: write fp32 C*scale.
// ===========================================================================
#define PADR 40   // smem row stride in bf16 (80 B skew, conflict-free ldmatrix)

template <int AM>
__global__ __launch_bounds__(256, 2) void tc_gemm_g(
    const __nv_bfloat16* __restrict__ Ahi, const __nv_bfloat16* __restrict__ Alo,
    int lda, long sAb, long sAh,
    const __nv_bfloat16* __restrict__ Bhi, const __nv_bfloat16* __restrict__ Blo,
    int ldb, long sBb, long sBh,
    __nv_bfloat16* __restrict__ Ohi, __nv_bfloat16* __restrict__ Olo,
    float* __restrict__ Of32, int ldo, long sOb, long sOh,
    int K, int Hn, float scale, int mode)
{
    constexpr int NT  = (AM == 2) ? 128 : 64;
    constexpr int ASZ = 128 * PADR;      // elems per A tile (hi or lo)
    constexpr int BSZ = NT * PADR;
    constexpr int STG = 2 * (ASZ + BSZ); // elems per stage
    extern __shared__ __nv_bfloat16 smem[];

    int z = blockIdx.z, zb = z / Hn, zh = z % Hn;
    Ahi += zb * sAb + zh * sAh;  Alo += zb * sAb + zh * sAh;
    Bhi += zb * sBb + zh * sBh;  Blo += zb * sBb + zh * sBh;
    long ob = zb * sOb + zh * sOh;

    int row0 = blockIdx.y * 128, col0 = blockIdx.x * NT;
    int tid = threadIdx.x, lane = tid & 31, wid = tid >> 5;
    int wm = (AM == 2) ? (wid & 3) : wid;
    int wn = (AM == 2) ? (wid >> 2) : 0;

    uint32_t sbase = smem_u32(smem);

    float acc[AM][8][4];
#pragma unroll
    for (int i = 0; i < AM; i++)
#pragma unroll
        for (int j = 0; j < 8; j++)
#pragma unroll
            for (int k = 0; k < 4; k++) acc[i][j][k] = 0.0f;

    // ldmatrix lane addressing (constant across chunks)
    int a_r = (lane & 15);
    int a_c = ((lane >> 4) << 3);
    int b_r = ((lane >> 4) << 3) + (lane & 7);
    int b_c = (((lane >> 3) & 1) << 3);

    auto load_chunk = [&](int c, int st) {
        int k0 = c * 32;
        uint32_t sb = sbase + (uint32_t)st * STG * 2;
#pragma unroll
        for (int t = 0; t < 2; t++) {
            int idx = tid + t * 256;
            int r = idx >> 2, v = idx & 3;
            long go = (long)(row0 + r) * lda + k0 + v * 8;
            uint32_t so = (uint32_t)(r * PADR + v * 8) * 2;
            CP_ASYNC16(sb + so, Ahi + go);
            CP_ASYNC16(sb + ASZ * 2 + so, Alo + go);
        }
#pragma unroll
        for (int t = 0; t < NT / 64; t++) {
            int idx = tid + t * 256;
            int r = idx >> 2, v = idx & 3;
            long go = (long)(col0 + r) * ldb + k0 + v * 8;
            uint32_t so = (uint32_t)(r * PADR + v * 8) * 2;
            CP_ASYNC16(sb + 2 * ASZ * 2 + so, Bhi + go);
            CP_ASYNC16(sb + (2 * ASZ + BSZ) * 2 + so, Blo + go);
        }
        CP_COMMIT();
    };

    int NCH = K / 32;
    load_chunk(0, 0);
    for (int c = 0; c < NCH; c++) {
        int st = c & 1;
        if (c + 1 < NCH) { load_chunk(c + 1, st ^ 1); CP_WAIT1(); }
        else             { CP_WAIT0(); }
        __syncthreads();

        uint32_t sb  = sbase + (uint32_t)st * STG * 2;
        uint32_t aHb = sb, aLb = sb + ASZ * 2;
        uint32_t bHb = sb + 2 * ASZ * 2, bLb = sb + (2 * ASZ + BSZ) * 2;
#pragma unroll
        for (int ks = 0; ks < 2; ks++) {
            int kb = ks * 16;
            uint32_t aH[AM][4], aL[AM][4];
#pragma unroll
            for (int am = 0; am < AM; am++) {
                uint32_t off =
                    (uint32_t)((wm * (16 * AM) + am * 16 + a_r) * PADR + kb + a_c) * 2;
                ldsm_x4(aHb + off, aH[am]);
                ldsm_x4(aLb + off, aL[am]);
            }
#pragma unroll
            for (int bp = 0; bp < 4; bp++) {
                uint32_t boff =
                    (uint32_t)((wn * 64 + bp * 16 + b_r) * PADR + kb + b_c) * 2;
                uint32_t bH[4], bL[4];
                ldsm_x4(bHb + boff, bH);
                ldsm_x4(bLb + boff, bL);
#pragma unroll
                for (int am = 0; am < AM; am++)
#pragma unroll
                    for (int bna = 0; bna < 2; bna++) {
                        float* cc = acc[am][bp * 2 + bna];
                        mma_bf16(cc, aH[am], bH + bna * 2);
                        mma_bf16(cc, aH[am], bL + bna * 2);
                        mma_bf16(cc, aL[am], bH + bna * 2);
                    }
            }
        }
        __syncthreads();
    }

    // Epilogue. C fragment: c0=(r,c), c1=(r,c+1), c2=(r+8,c), c3=(r+8,c+1)
    int r_base = row0 + wm * (16 * AM) + (lane >> 2);
    int c_base = col0 + wn * 64 + 2 * (lane & 3);
#pragma unroll
    for (int am = 0; am < AM; am++)
#pragma unroll
        for (int bn = 0; bn < 8; bn++) {
            int r = r_base + am * 16;
            int c = c_base + bn * 8;
            const float* a = acc[am][bn];
            if (mode == 0) {
#pragma unroll
                for (int hrow = 0; hrow < 2; hrow++) {
                    float f0 = a[hrow * 2], f1 = a[hrow * 2 + 1];
                    __nv_bfloat16 h0 = __float2bfloat16(f0);
                    __nv_bfloat16 h1 = __float2bfloat16(f1);
                    __nv_bfloat16 l0 = __float2bfloat16(f0 - __bfloat162float(h0));
                    __nv_bfloat16 l1 = __float2bfloat16(f1 - __bfloat162float(h1));
                    long o = ob + (long)(r + hrow * 8) * ldo + c;
                    *(__nv_bfloat162*)(Ohi + o) = __halves2bfloat162(h0, h1);
                    *(__nv_bfloat162*)(Olo + o) = __halves2bfloat162(l0, l1);
                }
            } else {
#pragma unroll
                for (int hrow = 0; hrow < 2; hrow++) {
                    long o = ob + (long)(r + hrow * 8) * ldo + c;
                    float2 f2;
                    f2.x = a[hrow * 2] * scale;
                    f2.y = a[hrow * 2 + 1] * scale;
                    *(float2*)(Of32 + o) = f2;
                }
            }
        }
}

// ===========================================================================
// Elementwise / conversion kernels
// ===========================================================================
__global__ __launch_bounds__(256) void split_kernel(
    const float* __restrict__ in, __nv_bfloat16* __restrict__ hi,
    __nv_bfloat16* __restrict__ lo, int n4)
{
    int i = blockIdx.x * 256 + threadIdx.x;
    if (i >= n4) return;
    float4 v = ((const float4*)in)[i];
    float f[4] = { v.x, v.y, v.z, v.w };
    __nv_bfloat16 h[4], l[4];
#pragma unroll
    for (int j = 0; j < 4; j++) {
        h[j] = __float2bfloat16(f[j]);
        l[j] = __float2bfloat16(f[j] - __bfloat162float(h[j]));
    }
    ((__nv_bfloat162*)hi)[2 * i]     = __halves2bfloat162(h[0], h[1]);
    ((__nv_bfloat162*)hi)[2 * i + 1] = __halves2bfloat162(h[2], h[3]);
    ((__nv_bfloat162*)lo)[2 * i]     = __halves2bfloat162(l[0], l[1]);
    ((__nv_bfloat162*)lo)[2 * i + 1] = __halves2bfloat162(l[2], l[3]);
}

// transpose + split: out[z][c][r] = split(in[z][r][c]); 512x512 per z
__global__ __launch_bounds__(256) void split_trans_kernel(
    const float* __restrict__ S, __nv_bfloat16* __restrict__ hi,
    __nv_bfloat16* __restrict__ lo)
{
    __shared__ float t[32][33];
    int z = blockIdx.z;
    long zo = (long)z * LL2;
    int c0 = blockIdx.x * 32, r0 = blockIdx.y * 32;
    int tx = threadIdx.x & 31, ty = threadIdx.x >> 5;
#pragma unroll
    for (int i = 0; i < 4; i++)
        t[ty + i * 8][tx] = S[zo + (long)(r0 + ty + i * 8) * Ll + c0 + tx];
    __syncthreads();
#pragma unroll
    for (int i = 0; i < 4; i++) {
        float v = t[tx][ty + i * 8];
        __nv_bfloat16 h = __float2bfloat16(v);
        __nv_bfloat16 l = __float2bfloat16(v - __bfloat162float(h));
        long o = zo + (long)(c0 + ty + i * 8) * Ll + r0 + tx;
        hi[o] = h;
        lo[o] = l;
    }
}

// V^T extraction (bf16 -> bf16): VT[z][d][j] = QKV[(b*512+j)*1536 + 1024 + h*64 + d]
__global__ __launch_bounds__(256) void vt_transpose(
    const __nv_bfloat16* __restrict__ Qh, const __nv_bfloat16* __restrict__ Ql,
    __nv_bfloat16* __restrict__ VTh, __nv_bfloat16* __restrict__ VTl)
{
    __shared__ __nv_bfloat16 th[32][72], tl[32][72];
    int z = blockIdx.z, b = z >> 3, h = z & 7;
    int j0 = blockIdx.x * 32;
    int t = threadIdx.x;
    int r = t >> 3, v = t & 7;
    long src = (long)(b * 512 + j0 + r) * 1536 + 1024 + h * 64 + v * 8;
    *(uint4*)&th[r][v * 8] = *(const uint4*)(Qh + src);
    *(uint4*)&tl[r][v * 8] = *(const uint4*)(Ql + src);
    __syncthreads();
    long zo = (long)z * HDd * Ll;
#pragma unroll
    for (int i = 0; i < 8; i++) {
        int e = t + i * 256;
        int d = e >> 5, j = e & 31;
        VTh[zo + (long)d * Ll + j0 + j] = th[j][d];
        VTl[zo + (long)d * Ll + j0 + j] = tl[j][d];
    }
}

// Fused A_hat + split (fp32 A_hat never materialized)
__global__ __launch_bounds__(256) void ahat_split_kernel(
    const float* __restrict__ A, const float* __restrict__ dinv,
    __nv_bfloat16* __restrict__ hi, __nv_bfloat16* __restrict__ lo)
{
    long n4 = (long)ZZ * Ll * Ll / 4;
    for (long i = (long)blockIdx.x * blockDim.x + threadIdx.x; i < n4;
         i += (long)gridDim.x * blockDim.x) {
        long x = i * 4;
        long z = x >> 18;
        int r = (int)((x >> 9) & 511);
        int c = (int)(x & 511);
        float dr = dinv[z * Ll + r];
        const float* dc = dinv + z * Ll + c;
        float4 v = ((const float4*)A)[i];
        float f[4] = { v.x, v.y, v.z, v.w };
#pragma unroll
        for (int j = 0; j < 4; j++) {
            float a = f[j] + ((c + j) == r ? 1.0f : 0.0f);
            f[j] = a * dr * dc[j];
        }
        __nv_bfloat16 h[4], l[4];
#pragma unroll
        for (int j = 0; j < 4; j++) {
            h[j] = __float2bfloat16(f[j]);
            l[j] = __float2bfloat16(f[j] - __bfloat162float(h[j]));
        }
        ((__nv_bfloat162*)hi)[2 * i]     = __halves2bfloat162(h[0], h[1]);
        ((__nv_bfloat162*)hi)[2 * i + 1] = __halves2bfloat162(h[2], h[3]);
        ((__nv_bfloat162*)lo)[2 * i]     = __halves2bfloat162(l[0], l[1]);
        ((__nv_bfloat162*)lo)[2 * i + 1] = __halves2bfloat162(l[2], l[3]);
    }
}

// ===========================================================================
// Adjacency (fp32 SIMT, symmetric tile pairs)
// ===========================================================================
__global__ __launch_bounds__(256) void adj_kernel(const float* __restrict__ S,
                                                  float* __restrict__ A)
{
    int z = blockIdx.z;
    const float* Sh = S + (long)z * Ll * Ll;
    float* Ah = A + (long)z * Ll * Ll;

    int rem = blockIdx.x;
    int ti = 0;
    while (rem >= (8 - ti)) { rem -= (8 - ti); ti++; }
    int tk = ti + rem;
    int i0 = ti * 64, k0 = tk * 64;

    __shared__ float Si[32][68];
    __shared__ float Sk[32][68];

    int tid = threadIdx.x;
    int tx = tid & 15, ty = tid >> 4;
    const float THR = 0.1f * 64.0f;

    float acc[4][4] = {};

    for (int j0 = 0; j0 < Ll; j0 += 32) {
#pragma unroll
        for (int t = 0; t < 8; t++) {
            int li = tid + t * 256;
            int i = li >> 5, j = li & 31;
            Si[j][i] = Sh[(long)(i0 + i) * Ll + j0 + j];
            Sk[j][i] = Sh[(long)(k0 + i) * Ll + j0 + j];
        }
        __syncthreads();
#pragma unroll
        for (int j = 0; j < 32; j++) {
            float4 av = *(const float4*)&Si[j][ty * 4];
            float4 bv = *(const float4*)&Sk[j][tx * 4];
            float a[4] = {av.x, av.y, av.z, av.w};
            float b[4] = {bv.x, bv.y, bv.z, bv.w};
#pragma unroll
            for (int ii = 0; ii < 4; ii++)
#pragma unroll
                for (int kk = 0; kk < 4; kk++) {
                    float t = a[ii] * b[kk];
                    if (t > THR) acc[ii][kk] += t;
                }
        }
        __syncthreads();
    }

    const float inv = 1.0f / (64.0f * 512.0f);
#pragma unroll
    for (int ii = 0; ii < 4; ii++)
#pragma unroll
        for (int kk = 0; kk < 4; kk++) {
            int gi = i0 + ty * 4 + ii, gk = k0 + tx * 4 + kk;
            float v = (gi == gk) ? 0.0f : acc[ii][kk] * inv;
            Ah[(long)gi * Ll + gk] = v;
            if (ti != tk) Ah[(long)gk * Ll + gi] = v;
        }
}

__global__ __launch_bounds__(256) void rowsum_kernel(const float* __restrict__ A,
                                                     float* __restrict__ dinv)
{
    long row = blockIdx.x;
    const float* a = A + row * Ll;
    int t = threadIdx.x;
    float s = a[t] + a[t + 256];
#pragma unroll
    for (int o = 16; o > 0; o >>= 1) s += __shfl_xor_sync(0xFFFFFFFFu, s, o);
    __shared__ float red[8];
    if ((t & 31) == 0) red[t >> 5] = s;
    __syncthreads();
    if (t == 0) {
        float tot = 1.0f;
        for (int w = 0; w < 8; w++) tot += red[w];
        tot = fmaxf(tot, 1e-6f);
        dinv[row] = rsqrtf(tot);
    }
}

// softmax fused with bf16 hi/lo split of the attn weights
__global__ __launch_bounds__(256) void softmax_split(
    const float* __restrict__ S, __nv_bfloat16* __restrict__ hi,
    __nv_bfloat16* __restrict__ lo)
{
    long row = blockIdx.x;
    const float* s = S + row * Ll;
    int t = threadIdx.x;
    float v0 = s[t], v1 = s[t + 256];

    __shared__ float red[8];
    float m = fmaxf(v0, v1);
#pragma unroll
    for (int o = 16; o > 0; o >>= 1) m = fmaxf(m, __shfl_xor_sync(0xFFFFFFFFu, m, o));
    if ((t & 31) == 0) red[t >> 5] = m;
    __syncthreads();
    float mm = red[0];
#pragma unroll
    for (int w = 1; w < 8; w++) mm = fmaxf(mm, red[w]);
    __syncthreads();

    float e0 = expf(v0 - mm), e1 = expf(v1 - mm);
    float ssum = e0 + e1;
#pragma unroll
    for (int o = 16; o > 0; o >>= 1) ssum += __shfl_xor_sync(0xFFFFFFFFu, ssum, o);
    if ((t & 31) == 0) red[t >> 5] = ssum;
    __syncthreads();
    float tot = 0.0f;
#pragma unroll
    for (int w = 0; w < 8; w++) tot += red[w];
    float inv = 1.0f / tot;
    float p0 = e0 * inv, p1 = e1 * inv;
    __nv_bfloat16 h0 = __float2bfloat16(p0);
    __nv_bfloat16 h1 = __float2bfloat16(p1);
    hi[row * Ll + t]       = h0;
    hi[row * Ll + t + 256] = h1;
    lo[row * Ll + t]       = __float2bfloat16(p0 - __bfloat162float(h0));
    lo[row * Ll + t + 256] = __float2bfloat16(p1 - __bfloat162float(h1));
}

// ===========================================================================
extern "C" void kernel_launch(void* const* d_in, const int* in_sizes, int n_in,
                              void* d_out, int out_size)
{
    const float* x  = (const float*)d_in[0];
    const float* Wq = (const float*)d_in[1];
    const float* Wk = (const float*)d_in[2];
    const float* Wv = (const float*)d_in[3];
    const float* Wo = (const float*)d_in[4];
    float* out = (float*)d_out;

    float *Sp, *Ap, *Dp;
    cudaGetSymbolAddress((void**)&Sp, g_S);
    cudaGetSymbolAddress((void**)&Ap, g_A);
    cudaGetSymbolAddress((void**)&Dp, g_dinv);

    __nv_bfloat16 *xH, *xL, *WTH, *WTL, *QKH, *QKL, *VTH, *VTL;
    __nv_bfloat16 *AhH, *AhL, *STH, *STL, *TH, *TL;
    cudaGetSymbolAddress((void**)&xH, g_x_hi);
    cudaGetSymbolAddress((void**)&xL, g_x_lo);
    cudaGetSymbolAddress((void**)&WTH, g_WT_hi);
    cudaGetSymbolAddress((void**)&WTL, g_WT_lo);
    cudaGetSymbolAddress((void**)&QKH, g_QKV_hi);
    cudaGetSymbolAddress((void**)&QKL, g_QKV_lo);
    cudaGetSymbolAddress((void**)&VTH, g_VT_hi);
    cudaGetSymbolAddress((void**)&VTL, g_VT_lo);
    cudaGetSymbolAddress((void**)&AhH, g_Ah_hi);
    cudaGetSymbolAddress((void**)&AhL, g_Ah_lo);
    cudaGetSymbolAddress((void**)&STH, g_ST_hi);
    cudaGetSymbolAddress((void**)&STL, g_ST_lo);
    cudaGetSymbolAddress((void**)&TH, g_T_hi);
    cudaGetSymbolAddress((void**)&TL, g_T_lo);

    // dynamic smem sizes: AM=2: 2*(2*128*40+2*128*40)*2 = 81920B; AM=1: 61440B
    const int SM2 = 2 * (2 * 128 * PADR + 2 * 128 * PADR) * 2;
    const int SM1 = 2 * (2 * 128 * PADR + 2 * 64 * PADR) * 2;
    cudaFuncSetAttribute(tc_gemm_g<2>, cudaFuncAttributeMaxDynamicSharedMemorySize, SM2);
    cudaFuncSetAttribute(tc_gemm_g<1>, cudaFuncAttributeMaxDynamicSharedMemorySize, SM1);

    // 0) operand splits
    split_kernel<<<1024, 256>>>(x, xH, xL, Bq * Ll * Dd / 4);
    split_trans_kernel<<<dim3(16, 16, 1), 256>>>(Wq, WTH, WTL);
    split_trans_kernel<<<dim3(16, 16, 1), 256>>>(Wk, WTH + 512 * 512, WTL + 512 * 512);
    split_trans_kernel<<<dim3(16, 16, 1), 256>>>(Wv, WTH + 2 * 512 * 512, WTL + 2 * 512 * 512);
    split_trans_kernel<<<dim3(16, 16, 1), 256>>>(Wo, WTH + 3L * 512 * 512, WTL + 3L * 512 * 512);

    // 1) QKV = x @ [Wq|Wk|Wv]  -> bf16 hi/lo [2048 x 1536]
    tc_gemm_g<2><<<dim3(12, 16, 1), 256, SM2>>>(
        xH, xL, Dd, 0, 0,
        WTH, WTL, Dd, 0, 0,
        QKH, QKL, nullptr, 3 * Dd, 0, 0,
        Dd, 1, 1.0f, 0);

    // 2) S = Q @ K^T per head -> fp32 g_S
    tc_gemm_g<2><<<dim3(4, 4, ZZ), 256, SM2>>>(
        QKH, QKL, 3 * Dd, (long)Ll * 3 * Dd, HDd,
        QKH + Dd, QKL + Dd, 3 * Dd, (long)Ll * 3 * Dd, HDd,
        nullptr, nullptr, Sp, Ll, (long)Hh * LL2, LL2,
        HDd, Hh, 1.0f, 1);

    // 3) adjacency / degrees / A_hat split
    adj_kernel<<<dim3(36, 1, ZZ), 256>>>(Sp, Ap);
    rowsum_kernel<<<ZZ * Ll, 256>>>(Ap, Dp);
    ahat_split_kernel<<<4096, 256>>>(Ap, Dp, AhH, AhL);

    // 4) S^T split (B operand of jump1)
    split_trans_kernel<<<dim3(16, 16, ZZ), 256>>>(Sp, STH, STL);

    // 5) T = A_hat @ S -> bf16 hi/lo
    tc_gemm_g<2><<<dim3(4, 4, ZZ), 256, SM2>>>(
        AhH, AhL, Ll, LL2, 0,
        STH, STL, Ll, LL2, 0,
        TH, TL, nullptr, Ll, LL2, 0,
        Ll, 1, 1.0f, 0);

    // 6) S_jump = (T @ A_hat) / 8 -> fp32 g_S
    tc_gemm_g<2><<<dim3(4, 4, ZZ), 256, SM2>>>(
        TH, TL, Ll, LL2, 0,
        AhH, AhL, Ll, LL2, 0,
        nullptr, nullptr, Sp, Ll, LL2, 0,
        Ll, 1, 0.125f, 1);

    // 7) softmax + attn split (into ST buffers, free after jump1)
    softmax_split<<<ZZ * Ll, 256>>>(Sp, STH, STL);

    // 8) V^T extraction from QKV
    vt_transpose<<<dim3(16, 1, ZZ), 256>>>(QKH, QKL, VTH, VTL);

    // 9) O = attn @ V -> bf16 hi/lo into T buffers ([b*512+i][h*64+d], ld 512)
    tc_gemm_g<1><<<dim3(1, 4, ZZ), 256, SM1>>>(
        STH, STL, Ll, (long)Hh * LL2, LL2,
        VTH, VTL, Ll, (long)Hh * HDd * Ll, (long)HDd * Ll,
        TH, TL, nullptr, Dd, (long)Ll * Dd, HDd,
        Ll, Hh, 1.0f, 0);

    // 10) out = O @ Wo -> fp32 d_out
    tc_gemm_g<2><<<dim3(4, 16, 1), 256, SM2>>>(
        TH, TL, Dd, 0, 0,
        WTH + 3L * 512 * 512, WTL + 3L * 512 * 512, Dd, 0, 0,
        nullptr, nullptr, out, Dd, 0, 0,
        Dd, 1, 1.0f, 1);
}